// round 9
// baseline (speedup 1.0000x reference)
#include <cuda_runtime.h>
#include <cuda_fp16.h>
#include <cstdint>

// ---------------------------------------------------------------------------
// AttentionLayer: B=2, S1=S2=2048, D=1024, H=16, dh=64
// out layout: [ output (2*2048*1024) | attn_weights (2*16*2048*2048) ] fp32
// GEMMs via mma.sync m16n8k16 (f16 in, f32 acc), fp16 hi/lo split (3 passes).
// Split is done ONCE per tensor (pre-kernel / producer epilogues), so GEMM
// main loops contain no cvt instructions.
// ---------------------------------------------------------------------------

#define BATCH 2
#define SEQ   2048
#define DEMB  1024
#define NHEAD 16
#define DHEAD 64

#define QKV_ELEMS (BATCH * SEQ * DEMB)          // 4,194,304
#define W_ELEMS   (DEMB * DEMB)                 // 1,048,576
#define ATTN_OFF  ((size_t)BATCH * SEQ * DEMB)

// split fp16 scratch (hi/lo pairs)
__device__ __half g_x1h[QKV_ELEMS], g_x1l[QKV_ELEMS];
__device__ __half g_x2h[QKV_ELEMS], g_x2l[QKV_ELEMS];
__device__ __half g_Wqh[W_ELEMS],  g_Wql[W_ELEMS];
__device__ __half g_Wkh[W_ELEMS],  g_Wkl[W_ELEMS];
__device__ __half g_Wvh[W_ELEMS],  g_Wvl[W_ELEMS];
__device__ __half g_Woh[W_ELEMS],  g_Wol[W_ELEMS];
__device__ __half g_Qh [QKV_ELEMS], g_Ql [QKV_ELEMS];
__device__ __half g_Kh [QKV_ELEMS], g_Kl [QKV_ELEMS];
__device__ __half g_Vth[QKV_ELEMS], g_Vtl[QKV_ELEMS];  // Vt: [(b*1024+h*64+d)][s]
__device__ __half g_AOh[QKV_ELEMS], g_AOl[QKV_ELEMS];

// ---------------------------------------------------------------------------
// helpers
// ---------------------------------------------------------------------------
__device__ __forceinline__ void cpasync16(void* dst_smem, const void* src_gmem) {
    uint32_t d = (uint32_t)__cvta_generic_to_shared(dst_smem);
    asm volatile("cp.async.cg.shared.global [%0], [%1], 16;\n" :: "r"(d), "l"(src_gmem));
}
#define CP_COMMIT()  asm volatile("cp.async.commit_group;\n" ::: "memory")
#define CP_WAIT(n)   asm volatile("cp.async.wait_group %0;\n" :: "n"(n) : "memory")

__device__ __forceinline__ void cvt2(float2 f, uint32_t& hi, uint32_t& lo) {
    __half2 h = __floats2half2_rn(f.x, f.y);
    float2 hf = __half22float2(h);
    __half2 l = __floats2half2_rn(f.x - hf.x, f.y - hf.y);
    hi = *reinterpret_cast<uint32_t*>(&h);
    lo = *reinterpret_cast<uint32_t*>(&l);
}
__device__ __forceinline__ void split1(float v, __half& h, __half& l) {
    h = __float2half_rn(v);
    l = __float2half_rn(v - __half2float(h));
}

__device__ __forceinline__ void mma16816(float* c, const uint32_t* a, const uint32_t* b) {
    asm volatile(
        "mma.sync.aligned.m16n8k16.row.col.f32.f16.f16.f32 "
        "{%0,%1,%2,%3}, {%4,%5,%6,%7}, {%8,%9}, {%0,%1,%2,%3};\n"
        : "+f"(c[0]), "+f"(c[1]), "+f"(c[2]), "+f"(c[3])
        : "r"(a[0]), "r"(a[1]), "r"(a[2]), "r"(a[3]), "r"(b[0]), "r"(b[1]));
}

__device__ __forceinline__ uint32_t lds_h2(const __half* p) {
    return *reinterpret_cast<const uint32_t*>(p);
}

// ---------------------------------------------------------------------------
// split kernel: fp32 -> fp16 hi/lo, vectorized x4
// ---------------------------------------------------------------------------
__global__ void split_f32(const float* __restrict__ src,
                          __half* __restrict__ h, __half* __restrict__ l, int n4)
{
    int i = blockIdx.x * blockDim.x + threadIdx.x;
    if (i >= n4) return;
    float4 v = reinterpret_cast<const float4*>(src)[i];
    __half2 h01 = __floats2half2_rn(v.x, v.y);
    __half2 h23 = __floats2half2_rn(v.z, v.w);
    float2 f01 = __half22float2(h01);
    float2 f23 = __half22float2(h23);
    __half2 l01 = __floats2half2_rn(v.x - f01.x, v.y - f01.y);
    __half2 l23 = __floats2half2_rn(v.z - f23.x, v.w - f23.y);
    reinterpret_cast<__half2*>(h)[i * 2]     = h01;
    reinterpret_cast<__half2*>(h)[i * 2 + 1] = h23;
    reinterpret_cast<__half2*>(l)[i * 2]     = l01;
    reinterpret_cast<__half2*>(l)[i * 2 + 1] = l23;
}

// ---------------------------------------------------------------------------
// gemm_ff: both operands pre-split fp16. C[m,n] = scale*sum A[m,k]B[n,k] (+bias)
// A: Ah/Al row-major [M,K] halves (lda), B: Bh/Bl [N,K] (ldb).
// BM=128, BN in {128,64}; 256 threads = 8 warps (2x4), warp tile 64 x BN/4.
// OUTMODE: 0 = fp32 out; 1 = split fp16 out (Ch/Cl); 2 = split fp16 transposed
// (Vt layout [(b*1024+col)][s]).
// ---------------------------------------------------------------------------
template <int BN, int OUTMODE>
__global__ void __launch_bounds__(256)
gemm_ff(const __half* __restrict__ Ah, const __half* __restrict__ Al,
        const __half* __restrict__ Bh, const __half* __restrict__ Bl,
        const float* __restrict__ bias,
        float* __restrict__ C, __half* __restrict__ Ch, __half* __restrict__ Cl,
        int K, int lda, int ldb, int ldc,
        size_t aOffB, size_t aOffH,
        size_t bOffB, size_t bOffH,
        size_t cOffB, size_t cOffH,
        float scale)
{
    constexpr int NT = BN / 32;
    __shared__ __half sAh[2][128][24], sAl[2][128][24];
    __shared__ __half sBh[2][BN][24],  sBl[2][BN][24];

    const int tid  = threadIdx.x;
    const int wid  = tid >> 5;
    const int lane = tid & 31;
    const int grp  = lane >> 2;
    const int qid  = lane & 3;
    const int wm   = (wid >> 2) * 64;
    const int wn   = (wid & 3) * (BN / 4);

    const int z    = blockIdx.z;
    const int bidx = z >> 4;
    const int h    = z & 15;
    const size_t aoff = (size_t)bidx * aOffB + (size_t)h * aOffH;
    const size_t boff = (size_t)bidx * bOffB + (size_t)h * bOffH;
    const size_t coff = (size_t)bidx * cOffB + (size_t)h * cOffH;
    Ah += aoff; Al += aoff;
    Bh += boff; Bl += boff;

    const int m0 = blockIdx.y * 128;
    const int n0 = blockIdx.x * BN;
    const __half* Abh = Ah + (size_t)m0 * lda;
    const __half* Abl = Al + (size_t)m0 * lda;
    const __half* Bbh = Bh + (size_t)n0 * ldb;
    const __half* Bbl = Bl + (size_t)n0 * ldb;

    float acc[4][NT][4];
#pragma unroll
    for (int mt = 0; mt < 4; mt++)
#pragma unroll
        for (int nt = 0; nt < NT; nt++)
#pragma unroll
            for (int i = 0; i < 4; i++) acc[mt][nt][i] = 0.f;

    const int NKB = K >> 4;

    auto load_stage = [&](int st, int k0) {
        // A: 128 rows x 16 halves (2 x 16B) x {hi,lo}
        {
            const int i = tid;              // 256 = 128*2
            const int r = i >> 1, c = (i & 1) * 8;
            cpasync16(&sAh[st][r][c], Abh + (size_t)r * lda + k0 + c);
            cpasync16(&sAl[st][r][c], Abl + (size_t)r * lda + k0 + c);
        }
        if (BN == 128) {
            const int i = tid;
            const int r = i >> 1, c = (i & 1) * 8;
            cpasync16(&sBh[st][r][c], Bbh + (size_t)r * ldb + k0 + c);
            cpasync16(&sBl[st][r][c], Bbl + (size_t)r * ldb + k0 + c);
        } else {
            if (tid < BN * 2) {
                const int r = tid >> 1, c = (tid & 1) * 8;
                cpasync16(&sBh[st][r][c], Bbh + (size_t)r * ldb + k0 + c);
                cpasync16(&sBl[st][r][c], Bbl + (size_t)r * ldb + k0 + c);
            }
        }
    };

    load_stage(0, 0);
    CP_COMMIT();

    for (int kb = 0; kb < NKB; kb++) {
        if (kb + 1 < NKB) {
            load_stage((kb + 1) & 1, (kb + 1) << 4);
            CP_COMMIT();
            CP_WAIT(1);
        } else {
            CP_WAIT(0);
        }
        __syncthreads();

        const int st = kb & 1;

        uint32_t aHi[4][4], aLo[4][4];
#pragma unroll
        for (int mt = 0; mt < 4; mt++) {
            const int r0 = wm + mt * 16 + grp;
            aHi[mt][0] = lds_h2(&sAh[st][r0    ][qid * 2    ]);
            aHi[mt][1] = lds_h2(&sAh[st][r0 + 8][qid * 2    ]);
            aHi[mt][2] = lds_h2(&sAh[st][r0    ][qid * 2 + 8]);
            aHi[mt][3] = lds_h2(&sAh[st][r0 + 8][qid * 2 + 8]);
            aLo[mt][0] = lds_h2(&sAl[st][r0    ][qid * 2    ]);
            aLo[mt][1] = lds_h2(&sAl[st][r0 + 8][qid * 2    ]);
            aLo[mt][2] = lds_h2(&sAl[st][r0    ][qid * 2 + 8]);
            aLo[mt][3] = lds_h2(&sAl[st][r0 + 8][qid * 2 + 8]);
        }
        uint32_t bHi[NT][2], bLo[NT][2];
#pragma unroll
        for (int nt = 0; nt < NT; nt++) {
            const int c0 = wn + nt * 8 + grp;
            bHi[nt][0] = lds_h2(&sBh[st][c0][qid * 2    ]);
            bHi[nt][1] = lds_h2(&sBh[st][c0][qid * 2 + 8]);
            bLo[nt][0] = lds_h2(&sBl[st][c0][qid * 2    ]);
            bLo[nt][1] = lds_h2(&sBl[st][c0][qid * 2 + 8]);
        }
#pragma unroll
        for (int mt = 0; mt < 4; mt++)
#pragma unroll
            for (int nt = 0; nt < NT; nt++) {
                mma16816(acc[mt][nt], aHi[mt], bHi[nt]);
                mma16816(acc[mt][nt], aHi[mt], bLo[nt]);
                mma16816(acc[mt][nt], aLo[mt], bHi[nt]);
            }
        __syncthreads();
    }

    // epilogue
#pragma unroll
    for (int mt = 0; mt < 4; mt++) {
#pragma unroll
        for (int nt = 0; nt < NT; nt++) {
            const float* cc = acc[mt][nt];
            const int row = m0 + wm + mt * 16 + grp;
            const int col = n0 + wn + nt * 8 + qid * 2;
            float b0 = bias ? bias[col]     : 0.f;
            float b1 = bias ? bias[col + 1] : 0.f;
            float v00 = cc[0] * scale + b0, v01 = cc[1] * scale + b1;
            float v10 = cc[2] * scale + b0, v11 = cc[3] * scale + b1;
            if (OUTMODE == 0) {
                float* Cb = C + coff;
                *reinterpret_cast<float2*>(&Cb[(size_t)row * ldc + col]) = make_float2(v00, v01);
                *reinterpret_cast<float2*>(&Cb[(size_t)(row + 8) * ldc + col]) = make_float2(v10, v11);
            } else if (OUTMODE == 1) {
                __half h00, h01, h10, h11, l00, l01, l10, l11;
                split1(v00, h00, l00); split1(v01, h01, l01);
                split1(v10, h10, l10); split1(v11, h11, l11);
                __half* Chb = Ch + coff;
                __half* Clb = Cl + coff;
                *reinterpret_cast<__half2*>(&Chb[(size_t)row * ldc + col]) = __halves2half2(h00, h01);
                *reinterpret_cast<__half2*>(&Clb[(size_t)row * ldc + col]) = __halves2half2(l00, l01);
                *reinterpret_cast<__half2*>(&Chb[(size_t)(row + 8) * ldc + col]) = __halves2half2(h10, h11);
                *reinterpret_cast<__half2*>(&Clb[(size_t)(row + 8) * ldc + col]) = __halves2half2(l10, l11);
            } else {
                // transposed split: Vt[(b*1024 + col)][s], s = row within batch
                const int b2 = row >> 11;
                const int s  = row & 2047;
                __half hh, ll;
                size_t p0 = ((size_t)(b2 * 1024 + col)) * 2048 + s;
                size_t p1 = ((size_t)(b2 * 1024 + col + 1)) * 2048 + s;
                split1(v00, hh, ll); Ch[p0] = hh;     Cl[p0] = ll;
                split1(v01, hh, ll); Ch[p1] = hh;     Cl[p1] = ll;
                split1(v10, hh, ll); Ch[p0 + 8] = hh; Cl[p0 + 8] = ll;
                split1(v11, hh, ll); Ch[p1 + 8] = hh; Cl[p1 + 8] = ll;
            }
        }
    }
}

// ---------------------------------------------------------------------------
// gemm_pv: A fp32 (P, in-loop split), B pre-split fp16 (Vt). Out: split fp16 AO.
// BM=128, BN=64. C[m,n] = sum_k A[m,k] * B[n,k].
// ---------------------------------------------------------------------------
__global__ void __launch_bounds__(256)
gemm_pv(const float* __restrict__ A,
        const __half* __restrict__ Bh, const __half* __restrict__ Bl,
        __half* __restrict__ Ch, __half* __restrict__ Cl,
        int K, int lda, int ldb, int ldc,
        size_t aOffB, size_t aOffH,
        size_t bOffB, size_t bOffH,
        size_t cOffB, size_t cOffH)
{
    constexpr int BN = 64;
    constexpr int NT = 2;
    __shared__ float  sA[2][128][20];
    __shared__ __half sBh[2][BN][24], sBl[2][BN][24];

    const int tid  = threadIdx.x;
    const int wid  = tid >> 5;
    const int lane = tid & 31;
    const int grp  = lane >> 2;
    const int qid  = lane & 3;
    const int wm   = (wid >> 2) * 64;
    const int wn   = (wid & 3) * 16;

    const int z    = blockIdx.z;
    const int bidx = z >> 4;
    const int h    = z & 15;
    A  += (size_t)bidx * aOffB + (size_t)h * aOffH;
    const size_t boff = (size_t)bidx * bOffB + (size_t)h * bOffH;
    Bh += boff; Bl += boff;
    const size_t coff = (size_t)bidx * cOffB + (size_t)h * cOffH;

    const int m0 = blockIdx.y * 128;
    const float* Ab = A + (size_t)m0 * lda;

    float acc[4][NT][4];
#pragma unroll
    for (int mt = 0; mt < 4; mt++)
#pragma unroll
        for (int nt = 0; nt < NT; nt++)
#pragma unroll
            for (int i = 0; i < 4; i++) acc[mt][nt][i] = 0.f;

    const int NKB = K >> 4;

    auto load_stage = [&](int st, int k0) {
#pragma unroll 2
        for (int i = tid; i < 128 * 4; i += 256) {
            const int r = i >> 2, sgm = i & 3;
            cpasync16(&sA[st][r][sgm * 4], Ab + (size_t)r * lda + k0 + sgm * 4);
        }
        if (tid < BN * 2) {
            const int r = tid >> 1, c = (tid & 1) * 8;
            cpasync16(&sBh[st][r][c], Bh + (size_t)r * ldb + k0 + c);
            cpasync16(&sBl[st][r][c], Bl + (size_t)r * ldb + k0 + c);
        }
    };

    load_stage(0, 0);
    CP_COMMIT();

    for (int kb = 0; kb < NKB; kb++) {
        if (kb + 1 < NKB) {
            load_stage((kb + 1) & 1, (kb + 1) << 4);
            CP_COMMIT();
            CP_WAIT(1);
        } else {
            CP_WAIT(0);
        }
        __syncthreads();

        const int st = kb & 1;

        uint32_t aHi[4][4], aLo[4][4];
#pragma unroll
        for (int mt = 0; mt < 4; mt++) {
            const int r0 = wm + mt * 16 + grp;
            float2 f00 = *reinterpret_cast<const float2*>(&sA[st][r0    ][qid * 2    ]);
            float2 f10 = *reinterpret_cast<const float2*>(&sA[st][r0 + 8][qid * 2    ]);
            float2 f01 = *reinterpret_cast<const float2*>(&sA[st][r0    ][qid * 2 + 8]);
            float2 f11 = *reinterpret_cast<const float2*>(&sA[st][r0 + 8][qid * 2 + 8]);
            cvt2(f00, aHi[mt][0], aLo[mt][0]);
            cvt2(f10, aHi[mt][1], aLo[mt][1]);
            cvt2(f01, aHi[mt][2], aLo[mt][2]);
            cvt2(f11, aHi[mt][3], aLo[mt][3]);
        }
        uint32_t bHi[NT][2], bLo[NT][2];
#pragma unroll
        for (int nt = 0; nt < NT; nt++) {
            const int c0 = wn + nt * 8 + grp;
            bHi[nt][0] = lds_h2(&sBh[st][c0][qid * 2    ]);
            bHi[nt][1] = lds_h2(&sBh[st][c0][qid * 2 + 8]);
            bLo[nt][0] = lds_h2(&sBl[st][c0][qid * 2    ]);
            bLo[nt][1] = lds_h2(&sBl[st][c0][qid * 2 + 8]);
        }
#pragma unroll
        for (int mt = 0; mt < 4; mt++)
#pragma unroll
            for (int nt = 0; nt < NT; nt++) {
                mma16816(acc[mt][nt], aHi[mt], bHi[nt]);
                mma16816(acc[mt][nt], aHi[mt], bLo[nt]);
                mma16816(acc[mt][nt], aLo[mt], bHi[nt]);
            }
        __syncthreads();
    }

#pragma unroll
    for (int mt = 0; mt < 4; mt++) {
#pragma unroll
        for (int nt = 0; nt < NT; nt++) {
            const float* cc = acc[mt][nt];
            const int row = m0 + wm + mt * 16 + grp;
            const int col = wn + nt * 8 + qid * 2;
            __half h00, h01, h10, h11, l00, l01, l10, l11;
            split1(cc[0], h00, l00); split1(cc[1], h01, l01);
            split1(cc[2], h10, l10); split1(cc[3], h11, l11);
            __half* Chb = Ch + coff;
            __half* Clb = Cl + coff;
            *reinterpret_cast<__half2*>(&Chb[(size_t)row * ldc + col]) = __halves2half2(h00, h01);
            *reinterpret_cast<__half2*>(&Clb[(size_t)row * ldc + col]) = __halves2half2(l00, l01);
            *reinterpret_cast<__half2*>(&Chb[(size_t)(row + 8) * ldc + col]) = __halves2half2(h10, h11);
            *reinterpret_cast<__half2*>(&Clb[(size_t)(row + 8) * ldc + col]) = __halves2half2(l10, l11);
        }
    }
}

// ---------------------------------------------------------------------------
// In-place row softmax: one block per row of 2048 floats, 256 threads x 8.
// ---------------------------------------------------------------------------
__global__ void softmax_rows(float* __restrict__ P)
{
    const size_t base = (size_t)blockIdx.x * 2048;
    float* p = P + base;
    const int tid = threadIdx.x;

    float v[8];
    float m = -1e30f;
#pragma unroll
    for (int i = 0; i < 8; i++) {
        v[i] = p[tid + i * 256];
        m = fmaxf(m, v[i]);
    }
#pragma unroll
    for (int o = 16; o > 0; o >>= 1) m = fmaxf(m, __shfl_xor_sync(0xffffffffu, m, o));

    __shared__ float redM[8];
    __shared__ float redS[8];
    if ((tid & 31) == 0) redM[tid >> 5] = m;
    __syncthreads();
    float mAll = redM[0];
#pragma unroll
    for (int w = 1; w < 8; w++) mAll = fmaxf(mAll, redM[w]);

    float s = 0.f;
#pragma unroll
    for (int i = 0; i < 8; i++) {
        v[i] = __expf(v[i] - mAll);
        s += v[i];
    }
#pragma unroll
    for (int o = 16; o > 0; o >>= 1) s += __shfl_xor_sync(0xffffffffu, s, o);
    if ((tid & 31) == 0) redS[tid >> 5] = s;
    __syncthreads();
    float sAll = 0.f;
#pragma unroll
    for (int w = 0; w < 8; w++) sAll += redS[w];

    const float inv = 1.f / sAll;
#pragma unroll
    for (int i = 0; i < 8; i++) p[tid + i * 256] = v[i] * inv;
}

// ---------------------------------------------------------------------------

extern "C" void kernel_launch(void* const* d_in, const int* in_sizes, int n_in,
                              void* d_out, int out_size)
{
    const float* x1 = (const float*)d_in[0];
    const float* x2 = (const float*)d_in[1];
    const float* Wq = (const float*)d_in[2];
    const float* bq = (const float*)d_in[3];
    const float* Wk = (const float*)d_in[4];
    const float* bk = (const float*)d_in[5];
    const float* Wv = (const float*)d_in[6];
    const float* bv = (const float*)d_in[7];
    const float* Wo = (const float*)d_in[8];
    const float* bo = (const float*)d_in[9];
    float* out = (float*)d_out;

    struct Ptrs {
        __half *x1h, *x1l, *x2h, *x2l;
        __half *Wqh, *Wql, *Wkh, *Wkl, *Wvh, *Wvl, *Woh, *Wol;
        __half *Qh, *Ql, *Kh, *Kl, *Vth, *Vtl, *AOh, *AOl;
        bool init;
    };
    static Ptrs P_ = { };
    if (!P_.init) {
        cudaGetSymbolAddress((void**)&P_.x1h, g_x1h); cudaGetSymbolAddress((void**)&P_.x1l, g_x1l);
        cudaGetSymbolAddress((void**)&P_.x2h, g_x2h); cudaGetSymbolAddress((void**)&P_.x2l, g_x2l);
        cudaGetSymbolAddress((void**)&P_.Wqh, g_Wqh); cudaGetSymbolAddress((void**)&P_.Wql, g_Wql);
        cudaGetSymbolAddress((void**)&P_.Wkh, g_Wkh); cudaGetSymbolAddress((void**)&P_.Wkl, g_Wkl);
        cudaGetSymbolAddress((void**)&P_.Wvh, g_Wvh); cudaGetSymbolAddress((void**)&P_.Wvl, g_Wvl);
        cudaGetSymbolAddress((void**)&P_.Woh, g_Woh); cudaGetSymbolAddress((void**)&P_.Wol, g_Wol);
        cudaGetSymbolAddress((void**)&P_.Qh,  g_Qh ); cudaGetSymbolAddress((void**)&P_.Ql,  g_Ql );
        cudaGetSymbolAddress((void**)&P_.Kh,  g_Kh ); cudaGetSymbolAddress((void**)&P_.Kl,  g_Kl );
        cudaGetSymbolAddress((void**)&P_.Vth, g_Vth); cudaGetSymbolAddress((void**)&P_.Vtl, g_Vtl);
        cudaGetSymbolAddress((void**)&P_.AOh, g_AOh); cudaGetSymbolAddress((void**)&P_.AOl, g_AOl);
        P_.init = true;
    }

    const size_t SD = (size_t)SEQ * DEMB;   // 2,097,152
    const size_t SS = (size_t)SEQ * SEQ;    // 4,194,304
    float* Pattn = out + ATTN_OFF;

    // 0) split inputs
    {
        const int n4x = QKV_ELEMS / 4, n4w = W_ELEMS / 4;
        split_f32<<<(n4x + 255) / 256, 256>>>(x1, P_.x1h, P_.x1l, n4x);
        split_f32<<<(n4x + 255) / 256, 256>>>(x2, P_.x2h, P_.x2l, n4x);
        split_f32<<<(n4w + 255) / 256, 256>>>(Wq, P_.Wqh, P_.Wql, n4w);
        split_f32<<<(n4w + 255) / 256, 256>>>(Wk, P_.Wkh, P_.Wkl, n4w);
        split_f32<<<(n4w + 255) / 256, 256>>>(Wv, P_.Wvh, P_.Wvl, n4w);
        split_f32<<<(n4w + 255) / 256, 256>>>(Wo, P_.Woh, P_.Wol, n4w);
    }

    // 1) projections: Q,K split fp16; V split fp16 transposed
    {
        dim3 grid(DEMB / 128, (BATCH * SEQ) / 128, 1);
        gemm_ff<128, 1><<<grid, 256>>>(P_.x1h, P_.x1l, P_.Wqh, P_.Wql, bq,
            nullptr, P_.Qh, P_.Ql, DEMB, DEMB, DEMB, DEMB, 0,0, 0,0, 0,0, 1.f);
        gemm_ff<128, 1><<<grid, 256>>>(P_.x2h, P_.x2l, P_.Wkh, P_.Wkl, bk,
            nullptr, P_.Kh, P_.Kl, DEMB, DEMB, DEMB, DEMB, 0,0, 0,0, 0,0, 1.f);
        gemm_ff<128, 2><<<grid, 256>>>(P_.x2h, P_.x2l, P_.Wvh, P_.Wvl, bv,
            nullptr, P_.Vth, P_.Vtl, DEMB, DEMB, DEMB, DEMB, 0,0, 0,0, 0,0, 1.f);
    }

    // 2) scores = Q K^T / 8 -> fp32 attn region
    {
        dim3 grid(SEQ / 128, SEQ / 128, BATCH * NHEAD);
        gemm_ff<128, 0><<<grid, 256>>>(P_.Qh, P_.Ql, P_.Kh, P_.Kl, nullptr,
            Pattn, nullptr, nullptr,
            DHEAD, DEMB, DEMB, SEQ,
            SD, (size_t)DHEAD,
            SD, (size_t)DHEAD,
            (size_t)NHEAD * SS, SS,
            0.125f);
    }

    // 3) softmax rows in place
    softmax_rows<<<BATCH * NHEAD * SEQ, 256>>>(Pattn);

    // 4) attn_out = P @ Vt^T -> split fp16 AO
    {
        dim3 grid(1, SEQ / 128, BATCH * NHEAD);
        gemm_pv<<<grid, 256>>>(Pattn, P_.Vth, P_.Vtl, P_.AOh, P_.AOl,
            SEQ, SEQ, SEQ, DEMB,
            (size_t)NHEAD * SS, SS,
            (size_t)(NHEAD * DHEAD) * SEQ, (size_t)DHEAD * SEQ,
            SD, (size_t)DHEAD);
    }

    // 5) output = AO @ Wo^T + bo -> fp32
    {
        dim3 grid(DEMB / 128, (BATCH * SEQ) / 128, 1);
        gemm_ff<128, 0><<<grid, 256>>>(P_.AOh, P_.AOl, P_.Woh, P_.Wol, bo,
            out, nullptr, nullptr, DEMB, DEMB, DEMB, DEMB, 0,0, 0,0, 0,0, 1.f);
    }
}

// round 13
// speedup vs baseline: 1.0209x; 1.0209x over previous
#include <cuda_runtime.h>
#include <cuda_fp16.h>
#include <cstdint>

// ---------------------------------------------------------------------------
// AttentionLayer: B=2, S1=S2=2048, D=1024, H=16, dh=64
// out layout: [ output (2*2048*1024) | attn_weights (2*16*2048*2048) ] fp32
// GEMMs via mma.sync m16n8k16 (f16 in, f32 acc), fp16 hi/lo split (3 passes).
// Softmax fused: scores kernel writes exp(s) + partial row sums; PV kernel
// normalizes P in-place and scales its accumulator. No standalone softmax.
// ---------------------------------------------------------------------------

#define BATCH 2
#define SEQ   2048
#define DEMB  1024
#define NHEAD 16
#define DHEAD 64

#define QKV_ELEMS (BATCH * SEQ * DEMB)          // 4,194,304
#define NROWS     (BATCH * NHEAD * SEQ)         // 65,536 attn rows
#define ATTN_OFF  ((size_t)BATCH * SEQ * DEMB)

// fp32 scratch
__device__ float g_Q [QKV_ELEMS];
__device__ float g_K [QKV_ELEMS];
__device__ float g_Vt[QKV_ELEMS];   // V transposed: [(b*1024 + h*64 + d)][s]
__device__ float g_AO[QKV_ELEMS];
__device__ float g_partial[16 * NROWS];  // per-colblock partial row sums
__device__ float g_inv[NROWS];           // 1 / rowsum

// ---------------------------------------------------------------------------
// helpers
// ---------------------------------------------------------------------------
__device__ __forceinline__ void cpasync16(void* dst_smem, const void* src_gmem) {
    uint32_t d = (uint32_t)__cvta_generic_to_shared(dst_smem);
    asm volatile("cp.async.cg.shared.global [%0], [%1], 16;\n" :: "r"(d), "l"(src_gmem));
}
#define CP_COMMIT()  asm volatile("cp.async.commit_group;\n" ::: "memory")
#define CP_WAIT(n)   asm volatile("cp.async.wait_group %0;\n" :: "n"(n) : "memory")

__device__ __forceinline__ void cvt2(float2 f, uint32_t& hi, uint32_t& lo) {
    __half2 h = __floats2half2_rn(f.x, f.y);
    float2 hf = __half22float2(h);
    __half2 l = __floats2half2_rn(f.x - hf.x, f.y - hf.y);
    hi = *reinterpret_cast<uint32_t*>(&h);
    lo = *reinterpret_cast<uint32_t*>(&l);
}

__device__ __forceinline__ void mma16816(float* c, const uint32_t* a, const uint32_t* b) {
    asm volatile(
        "mma.sync.aligned.m16n8k16.row.col.f32.f16.f16.f32 "
        "{%0,%1,%2,%3}, {%4,%5,%6,%7}, {%8,%9}, {%0,%1,%2,%3};\n"
        : "+f"(c[0]), "+f"(c[1]), "+f"(c[2]), "+f"(c[3])
        : "r"(a[0]), "r"(a[1]), "r"(a[2]), "r"(a[3]), "r"(b[0]), "r"(b[1]));
}

// ---------------------------------------------------------------------------
// gemm_mma: C[m,n] = f( scale * sum_k A[m,k]*B[n,k] (+ bias[n]) )
// A row-major [M,K] fp32 (lda), B row-major [N,K] fp32 (ldb).
// BM=128, BN in {128,64}; 256 threads = 8 warps (2x4), warp tile 64 x BN/4.
// OUTMODE 0: fp32 out (scale, +bias)
// OUTMODE 1: fp32 transposed out into Vt layout [(b*1024+col)][s] (+bias)
// OUTMODE 2: exp(scale*acc) out + per-(colblock,row) partial sums to `partial`
// ---------------------------------------------------------------------------
template <int BN, int OUTMODE>
__global__ void __launch_bounds__(256)
gemm_mma(const float* __restrict__ A, const float* __restrict__ B,
         const float* __restrict__ bias, float* __restrict__ C,
         float* __restrict__ partial,
         int K, int lda, int ldb, int ldc,
         size_t aOffB, size_t aOffH,
         size_t bOffB, size_t bOffH,
         size_t cOffB, size_t cOffH,
         float scale)
{
    constexpr int NT = BN / 32;
    __shared__ float sA[2][128][20];
    __shared__ float sB[2][BN][20];
    __shared__ float sred[4][128];   // OUTMODE 2 row-sum staging

    const int tid  = threadIdx.x;
    const int wid  = tid >> 5;
    const int lane = tid & 31;
    const int grp  = lane >> 2;
    const int qid  = lane & 3;
    const int wm   = (wid >> 2) * 64;
    const int wn   = (wid & 3) * (BN / 4);

    const int z    = blockIdx.z;
    const int bidx = z >> 4;
    const int h    = z & 15;
    A += (size_t)bidx * aOffB + (size_t)h * aOffH;
    B += (size_t)bidx * bOffB + (size_t)h * bOffH;
    float* Cb = C + (size_t)bidx * cOffB + (size_t)h * cOffH;

    const int m0 = blockIdx.y * 128;
    const int n0 = blockIdx.x * BN;
    const float* Ab = A + (size_t)m0 * lda;
    const float* Bb = B + (size_t)n0 * ldb;

    float acc[4][NT][4];
#pragma unroll
    for (int mt = 0; mt < 4; mt++)
#pragma unroll
        for (int nt = 0; nt < NT; nt++)
#pragma unroll
            for (int i = 0; i < 4; i++) acc[mt][nt][i] = 0.f;

    const int NKB = K >> 4;

    auto load_stage = [&](int st, int k0) {
#pragma unroll 2
        for (int i = tid; i < 128 * 4; i += 256) {
            const int r = i >> 2, sgm = i & 3;
            cpasync16(&sA[st][r][sgm * 4], Ab + (size_t)r * lda + k0 + sgm * 4);
        }
#pragma unroll 1
        for (int i = tid; i < BN * 4; i += 256) {
            const int r = i >> 2, sgm = i & 3;
            cpasync16(&sB[st][r][sgm * 4], Bb + (size_t)r * ldb + k0 + sgm * 4);
        }
    };

    load_stage(0, 0);
    CP_COMMIT();

    for (int kb = 0; kb < NKB; kb++) {
        if (kb + 1 < NKB) {
            load_stage((kb + 1) & 1, (kb + 1) << 4);
            CP_COMMIT();
            CP_WAIT(1);
        } else {
            CP_WAIT(0);
        }
        __syncthreads();

        const int st = kb & 1;

        uint32_t aHi[4][4], aLo[4][4];
#pragma unroll
        for (int mt = 0; mt < 4; mt++) {
            const int r0 = wm + mt * 16 + grp;
            float2 f00 = *reinterpret_cast<const float2*>(&sA[st][r0    ][qid * 2    ]);
            float2 f10 = *reinterpret_cast<const float2*>(&sA[st][r0 + 8][qid * 2    ]);
            float2 f01 = *reinterpret_cast<const float2*>(&sA[st][r0    ][qid * 2 + 8]);
            float2 f11 = *reinterpret_cast<const float2*>(&sA[st][r0 + 8][qid * 2 + 8]);
            cvt2(f00, aHi[mt][0], aLo[mt][0]);
            cvt2(f10, aHi[mt][1], aLo[mt][1]);
            cvt2(f01, aHi[mt][2], aLo[mt][2]);
            cvt2(f11, aHi[mt][3], aLo[mt][3]);
        }
        uint32_t bHi[NT][2], bLo[NT][2];
#pragma unroll
        for (int nt = 0; nt < NT; nt++) {
            const int c0 = wn + nt * 8 + grp;
            float2 g0 = *reinterpret_cast<const float2*>(&sB[st][c0][qid * 2    ]);
            float2 g1 = *reinterpret_cast<const float2*>(&sB[st][c0][qid * 2 + 8]);
            cvt2(g0, bHi[nt][0], bLo[nt][0]);
            cvt2(g1, bHi[nt][1], bLo[nt][1]);
        }
#pragma unroll
        for (int mt = 0; mt < 4; mt++)
#pragma unroll
            for (int nt = 0; nt < NT; nt++) {
                mma16816(acc[mt][nt], aHi[mt], bHi[nt]);
                mma16816(acc[mt][nt], aHi[mt], bLo[nt]);
                mma16816(acc[mt][nt], aLo[mt], bHi[nt]);
            }
        __syncthreads();
    }

    // ---------------- epilogue ----------------
    if (OUTMODE == 2) {
        float rs0[4] = {0.f, 0.f, 0.f, 0.f};
        float rs1[4] = {0.f, 0.f, 0.f, 0.f};
#pragma unroll
        for (int mt = 0; mt < 4; mt++) {
#pragma unroll
            for (int nt = 0; nt < NT; nt++) {
                const float* cc = acc[mt][nt];
                const int row = m0 + wm + mt * 16 + grp;
                const int col = n0 + wn + nt * 8 + qid * 2;
                float e00 = __expf(cc[0] * scale);
                float e01 = __expf(cc[1] * scale);
                float e10 = __expf(cc[2] * scale);
                float e11 = __expf(cc[3] * scale);
                rs0[mt] += e00 + e01;
                rs1[mt] += e10 + e11;
                *reinterpret_cast<float2*>(&Cb[(size_t)row * ldc + col]) = make_float2(e00, e01);
                *reinterpret_cast<float2*>(&Cb[(size_t)(row + 8) * ldc + col]) = make_float2(e10, e11);
            }
        }
        // reduce over qid lanes (cols within warp), stage per-warp sums
#pragma unroll
        for (int mt = 0; mt < 4; mt++) {
            float s0 = rs0[mt], s1 = rs1[mt];
            s0 += __shfl_xor_sync(0xffffffffu, s0, 1);
            s0 += __shfl_xor_sync(0xffffffffu, s0, 2);
            s1 += __shfl_xor_sync(0xffffffffu, s1, 1);
            s1 += __shfl_xor_sync(0xffffffffu, s1, 2);
            if (qid == 0) {
                sred[wid & 3][wm + mt * 16 + grp]     = s0;
                sred[wid & 3][wm + mt * 16 + grp + 8] = s1;
            }
        }
        __syncthreads();
        if (tid < 128) {
            float p = sred[0][tid] + sred[1][tid] + sred[2][tid] + sred[3][tid];
            partial[(size_t)blockIdx.x * NROWS + (size_t)z * SEQ + m0 + tid] = p;
        }
        return;
    }

#pragma unroll
    for (int mt = 0; mt < 4; mt++) {
#pragma unroll
        for (int nt = 0; nt < NT; nt++) {
            const float* cc = acc[mt][nt];
            const int row = m0 + wm + mt * 16 + grp;
            const int col = n0 + wn + nt * 8 + qid * 2;
            float b0 = bias ? bias[col]     : 0.f;
            float b1 = bias ? bias[col + 1] : 0.f;
            float v00 = cc[0] * scale + b0, v01 = cc[1] * scale + b1;
            float v10 = cc[2] * scale + b0, v11 = cc[3] * scale + b1;
            if (OUTMODE == 0) {
                *reinterpret_cast<float2*>(&Cb[(size_t)row * ldc + col]) = make_float2(v00, v01);
                *reinterpret_cast<float2*>(&Cb[(size_t)(row + 8) * ldc + col]) = make_float2(v10, v11);
            } else {
                // transposed into Vt[(b*1024 + col)][s]
                const int b2 = row >> 11;
                const int s  = row & 2047;
                C[((size_t)(b2 * 1024 + col    )) * 2048 + s]     = v00;
                C[((size_t)(b2 * 1024 + col + 1)) * 2048 + s]     = v01;
                C[((size_t)(b2 * 1024 + col    )) * 2048 + s + 8] = v10;
                C[((size_t)(b2 * 1024 + col + 1)) * 2048 + s + 8] = v11;
            }
        }
    }
}

// ---------------------------------------------------------------------------
// reduce_inv: inv[r] = 1 / sum_b partial[b][r]
// ---------------------------------------------------------------------------
__global__ void reduce_inv(const float* __restrict__ partial, float* __restrict__ inv)
{
    const int r = blockIdx.x * blockDim.x + threadIdx.x;
    if (r >= NROWS) return;
    float s = 0.f;
#pragma unroll
    for (int b = 0; b < 16; b++) s += partial[(size_t)b * NROWS + r];
    inv[r] = 1.f / s;
}

// ---------------------------------------------------------------------------
// gemm_pv: AO[m,n] = inv[m] * sum_k P[m,k] * Vt[n,k]; also writes back
// P[m,k] *= inv[m] (the final normalized attn_weights).
// BM=128, BN=64. P fp32 (in-loop hi/lo split), Vt fp32.
// ---------------------------------------------------------------------------
__global__ void __launch_bounds__(256)
gemm_pv(float* __restrict__ Pmat, const float* __restrict__ Bm,
        const float* __restrict__ inv, float* __restrict__ Cm,
        int K, int lda, int ldb, int ldc,
        size_t aOffB, size_t aOffH,
        size_t bOffB, size_t bOffH,
        size_t cOffB, size_t cOffH)
{
    constexpr int BN = 64;
    constexpr int NT = 2;
    __shared__ float sA[2][128][20];
    __shared__ float sB[2][BN][20];

    const int tid  = threadIdx.x;
    const int wid  = tid >> 5;
    const int lane = tid & 31;
    const int grp  = lane >> 2;
    const int qid  = lane & 3;
    const int wm   = (wid >> 2) * 64;
    const int wn   = (wid & 3) * 16;

    const int z    = blockIdx.z;
    const int bidx = z >> 4;
    const int h    = z & 15;
    float* Ap = Pmat + (size_t)bidx * aOffB + (size_t)h * aOffH;
    const float* Bp = Bm + (size_t)bidx * bOffB + (size_t)h * bOffH;
    float* Cb = Cm + (size_t)bidx * cOffB + (size_t)h * cOffH;

    const int m0 = blockIdx.y * 128;
    float* Ab = Ap + (size_t)m0 * lda;

    // per-thread fixed writeback row
    const int wbR = tid >> 1;
    const int wbC = (tid & 1) * 8;
    const float wbInv = inv[(size_t)z * SEQ + m0 + wbR];

    float acc[4][NT][4];
#pragma unroll
    for (int mt = 0; mt < 4; mt++)
#pragma unroll
        for (int nt = 0; nt < NT; nt++)
#pragma unroll
            for (int i = 0; i < 4; i++) acc[mt][nt][i] = 0.f;

    const int NKB = K >> 4;

    auto load_stage = [&](int st, int k0) {
#pragma unroll 2
        for (int i = tid; i < 128 * 4; i += 256) {
            const int r = i >> 2, sgm = i & 3;
            cpasync16(&sA[st][r][sgm * 4], Ab + (size_t)r * lda + k0 + sgm * 4);
        }
        if (tid < BN * 4) {
            const int r = tid >> 2, sgm = tid & 3;
            cpasync16(&sB[st][r][sgm * 4], Bp + (size_t)r * ldb + k0 + sgm * 4);
        }
    };

    load_stage(0, 0);
    CP_COMMIT();

    for (int kb = 0; kb < NKB; kb++) {
        if (kb + 1 < NKB) {
            load_stage((kb + 1) & 1, (kb + 1) << 4);
            CP_COMMIT();
            CP_WAIT(1);
        } else {
            CP_WAIT(0);
        }
        __syncthreads();

        const int st = kb & 1;
        const int k0 = kb << 4;

        // normalized write-back of this P tile (final attn_weights)
        {
            float4 v0 = *reinterpret_cast<const float4*>(&sA[st][wbR][wbC]);
            float4 v1 = *reinterpret_cast<const float4*>(&sA[st][wbR][wbC + 4]);
            v0.x *= wbInv; v0.y *= wbInv; v0.z *= wbInv; v0.w *= wbInv;
            v1.x *= wbInv; v1.y *= wbInv; v1.z *= wbInv; v1.w *= wbInv;
            float* dst = Ab + (size_t)wbR * lda + k0 + wbC;
            *reinterpret_cast<float4*>(dst)     = v0;
            *reinterpret_cast<float4*>(dst + 4) = v1;
        }

        uint32_t aHi[4][4], aLo[4][4];
#pragma unroll
        for (int mt = 0; mt < 4; mt++) {
            const int r0 = wm + mt * 16 + grp;
            float2 f00 = *reinterpret_cast<const float2*>(&sA[st][r0    ][qid * 2    ]);
            float2 f10 = *reinterpret_cast<const float2*>(&sA[st][r0 + 8][qid * 2    ]);
            float2 f01 = *reinterpret_cast<const float2*>(&sA[st][r0    ][qid * 2 + 8]);
            float2 f11 = *reinterpret_cast<const float2*>(&sA[st][r0 + 8][qid * 2 + 8]);
            cvt2(f00, aHi[mt][0], aLo[mt][0]);
            cvt2(f10, aHi[mt][1], aLo[mt][1]);
            cvt2(f01, aHi[mt][2], aLo[mt][2]);
            cvt2(f11, aHi[mt][3], aLo[mt][3]);
        }
        uint32_t bHi[NT][2], bLo[NT][2];
#pragma unroll
        for (int nt = 0; nt < NT; nt++) {
            const int c0 = wn + nt * 8 + grp;
            float2 g0 = *reinterpret_cast<const float2*>(&sB[st][c0][qid * 2    ]);
            float2 g1 = *reinterpret_cast<const float2*>(&sB[st][c0][qid * 2 + 8]);
            cvt2(g0, bHi[nt][0], bLo[nt][0]);
            cvt2(g1, bHi[nt][1], bLo[nt][1]);
        }
#pragma unroll
        for (int mt = 0; mt < 4; mt++)
#pragma unroll
            for (int nt = 0; nt < NT; nt++) {
                mma16816(acc[mt][nt], aHi[mt], bHi[nt]);
                mma16816(acc[mt][nt], aHi[mt], bLo[nt]);
                mma16816(acc[mt][nt], aLo[mt], bHi[nt]);
            }
        __syncthreads();
    }

#pragma unroll
    for (int mt = 0; mt < 4; mt++) {
        const int row = m0 + wm + mt * 16 + grp;
        const float i0 = inv[(size_t)z * SEQ + row];
        const float i1 = inv[(size_t)z * SEQ + row + 8];
#pragma unroll
        for (int nt = 0; nt < NT; nt++) {
            const float* cc = acc[mt][nt];
            const int col = wn + nt * 8 + qid * 2;
            *reinterpret_cast<float2*>(&Cb[(size_t)row * ldc + col]) =
                make_float2(cc[0] * i0, cc[1] * i0);
            *reinterpret_cast<float2*>(&Cb[(size_t)(row + 8) * ldc + col]) =
                make_float2(cc[2] * i1, cc[3] * i1);
        }
    }
}

// ---------------------------------------------------------------------------

extern "C" void kernel_launch(void* const* d_in, const int* in_sizes, int n_in,
                              void* d_out, int out_size)
{
    const float* x1 = (const float*)d_in[0];
    const float* x2 = (const float*)d_in[1];
    const float* Wq = (const float*)d_in[2];
    const float* bq = (const float*)d_in[3];
    const float* Wk = (const float*)d_in[4];
    const float* bk = (const float*)d_in[5];
    const float* Wv = (const float*)d_in[6];
    const float* bv = (const float*)d_in[7];
    const float* Wo = (const float*)d_in[8];
    const float* bo = (const float*)d_in[9];
    float* out = (float*)d_out;

    static float *Q = nullptr, *K = nullptr, *Vt = nullptr, *AO = nullptr,
                 *PART = nullptr, *INV = nullptr;
    if (Q == nullptr) {
        cudaGetSymbolAddress((void**)&Q,    g_Q);
        cudaGetSymbolAddress((void**)&K,    g_K);
        cudaGetSymbolAddress((void**)&Vt,   g_Vt);
        cudaGetSymbolAddress((void**)&AO,   g_AO);
        cudaGetSymbolAddress((void**)&PART, g_partial);
        cudaGetSymbolAddress((void**)&INV,  g_inv);
    }

    const size_t SD = (size_t)SEQ * DEMB;   // 2,097,152
    const size_t SS = (size_t)SEQ * SEQ;    // 4,194,304
    float* Pattn = out + ATTN_OFF;

    // 1) Q/K projections ; V projection -> transposed Vt
    {
        dim3 grid(DEMB / 128, (BATCH * SEQ) / 128, 1);
        gemm_mma<128, 0><<<grid, 256>>>(x1, Wq, bq, Q, nullptr,
            DEMB, DEMB, DEMB, DEMB, 0,0, 0,0, 0,0, 1.f);
        gemm_mma<128, 0><<<grid, 256>>>(x2, Wk, bk, K, nullptr,
            DEMB, DEMB, DEMB, DEMB, 0,0, 0,0, 0,0, 1.f);
        gemm_mma<128, 1><<<grid, 256>>>(x2, Wv, bv, Vt, nullptr,
            DEMB, DEMB, DEMB, DEMB, 0,0, 0,0, 0,0, 1.f);
    }

    // 2) P = exp(Q K^T / 8) (unnormalized) + partial row sums
    {
        dim3 grid(SEQ / 128, SEQ / 128, BATCH * NHEAD);
        gemm_mma<128, 2><<<grid, 256>>>(Q, K, nullptr, Pattn, PART,
            DHEAD, DEMB, DEMB, SEQ,
            SD, (size_t)DHEAD,
            SD, (size_t)DHEAD,
            (size_t)NHEAD * SS, SS,
            0.125f);
    }

    // 3) row-sum inverse
    reduce_inv<<<NROWS / 256, 256>>>(PART, INV);

    // 4) AO = inv * (P @ Vt^T); P normalized in-place (final attn_weights)
    {
        dim3 grid(1, SEQ / 128, BATCH * NHEAD);
        gemm_pv<<<grid, 256>>>(Pattn, Vt, INV, AO,
            SEQ, SEQ, SEQ, DEMB,
            (size_t)NHEAD * SS, SS,
            (size_t)(NHEAD * DHEAD) * SEQ, (size_t)DHEAD * SEQ,
            SD, (size_t)DHEAD);
    }

    // 5) output = AO @ Wo^T + bo
    {
        dim3 grid(DEMB / 128, (BATCH * SEQ) / 128, 1);
        gemm_mma<128, 0><<<grid, 256>>>(AO, Wo, bo, out, nullptr,
            DEMB, DEMB, DEMB, DEMB, 0,0, 0,0, 0,0, 1.f);
    }
}